// round 2
// baseline (speedup 1.0000x reference)
#include <cuda_runtime.h>
#include <cstdint>

// Problem shape (fixed by the reference):
//   graph_lstm_output: [B=4, S=256, C=128] f32   (d_in[0])
//   slic_output:       [B=4, H=512, W=512] i32   (d_in[1])
//   out:               [B, H, W, C] f32
//
// out[b,h,w,:] = graph_lstm_output[b, slic[b,h,w]-1, :]
//
// Pure HBM-write-bound gather: 512 MB out, 4 MB idx, 0.5 MB table (L2-resident).
// One thread per float4; 32 consecutive threads (one warp) cover one pixel.

static constexpr int B = 4;
static constexpr int S = 256;
static constexpr int C = 128;          // 128 f32 = 32 float4 per pixel
static constexpr int HW = 512 * 512;   // pixels per batch, 2^18
static constexpr int NPIX = B * HW;    // 2^20 pixels
static constexpr int V4_PER_PIX = C / 4;  // 32

__global__ __launch_bounds__(256, 8)
void convert2image_gather(const float4* __restrict__ src,   // [B*S, 32] float4 rows
                          const int*    __restrict__ slic,  // [NPIX]
                          float4*       __restrict__ out)   // [NPIX, 32]
{
    // Global float4 index; 2^25 total, grid covers exactly.
    unsigned int t = blockIdx.x * blockDim.x + threadIdx.x;

    unsigned int pix  = t >> 5;     // 32 float4 per pixel
    unsigned int lane = t & 31;

    // Uniform per-warp load (all 32 lanes hit the same address -> 1 sector).
    int seg = __ldg(&slic[pix]) - 1;            // 0-based segment id
    unsigned int b = pix >> 18;                 // pix / (512*512)

    // Source row: graph_lstm_output[b, seg, :] as 32 float4 (512 B, L2-hot).
    const float4* row = src + ((b << 8) + (unsigned)seg) * (unsigned)V4_PER_PIX;

    // Coalesced 512 B STG.128 burst per warp; output is write-once streaming.
    out[t] = row[lane];
}

extern "C" void kernel_launch(void* const* d_in, const int* in_sizes, int n_in,
                              void* d_out, int out_size)
{
    const float4* src  = (const float4*)d_in[0];
    const int*    slic = (const int*)d_in[1];
    float4*       out  = (float4*)d_out;

    const int total_v4 = NPIX * V4_PER_PIX;     // 2^25 = 33,554,432
    const int threads  = 256;
    const int blocks   = total_v4 / threads;    // 131,072 — exact, no tail

    convert2image_gather<<<blocks, threads>>>(src, slic, out);
}

// round 3
// speedup vs baseline: 1.5545x; 1.5545x over previous
#include <cuda_runtime.h>
#include <cstdint>

// Problem shape (fixed by the reference):
//   graph_lstm_output: [B=4, S=256, C=128] f32   (d_in[0])
//   slic_output:       [B=4, H=512, W=512] i32   (d_in[1])
//   out:               [B, H, W, C] f32
//
// out[b,h,w,:] = graph_lstm_output[b, slic[b,h,w]-1, :]
//
// Latency-bound gather last round (DRAM 49%, issue 17%): the per-warp
// slic->row->store chain (~850 cyc) moved only 512 B. This version gives each
// thread 4 independent chunks (grid-strided by total/4) so 4 chains overlap.

static constexpr int B = 4;
static constexpr int S = 256;
static constexpr int C = 128;              // 32 float4 per pixel
static constexpr int HW = 512 * 512;       // 2^18 pixels per batch
static constexpr int NPIX = B * HW;        // 2^20
static constexpr int V4_PER_PIX = C / 4;   // 32
static constexpr unsigned TOTAL_V4 = (unsigned)NPIX * V4_PER_PIX;  // 2^25
static constexpr int UNROLL = 4;
static constexpr unsigned CHUNK = TOTAL_V4 / UNROLL;               // 2^23

__global__ __launch_bounds__(256, 8)
void convert2image_gather4(const float4* __restrict__ src,   // [B*S, 32] float4 rows
                           const int*    __restrict__ slic,  // [NPIX]
                           float4*       __restrict__ out)   // [NPIX, 32]
{
    const unsigned t = blockIdx.x * blockDim.x + threadIdx.x;  // [0, CHUNK)

    unsigned idx[UNROLL];
    const float4* rowp[UNROLL];

    // Phase 1: all index loads + address math (4 independent slic loads in flight).
    #pragma unroll
    for (int i = 0; i < UNROLL; i++) {
        idx[i] = t + (unsigned)i * CHUNK;
        unsigned pix  = idx[i] >> 5;           // float4 -> pixel
        // slic is streamed once; bypass L1 so the table stays resident there.
        int seg = __ldcs(&slic[pix]) - 1;      // 0-based segment
        unsigned b = pix >> 18;                // pixel / (512*512)
        rowp[i] = src + (((b << 8) + (unsigned)seg) << 5);  // *32 float4
    }

    // Phase 2: 4 independent gather loads (table is L2/L1-hot, 512 KB total).
    float4 v[UNROLL];
    #pragma unroll
    for (int i = 0; i < UNROLL; i++)
        v[i] = __ldg(&rowp[i][idx[i] & 31]);

    // Phase 3: 4 coalesced streaming stores (write-once, evict-first in L2).
    #pragma unroll
    for (int i = 0; i < UNROLL; i++)
        __stcs(&out[idx[i]], v[i]);
}

extern "C" void kernel_launch(void* const* d_in, const int* in_sizes, int n_in,
                              void* d_out, int out_size)
{
    const float4* src  = (const float4*)d_in[0];
    const int*    slic = (const int*)d_in[1];
    float4*       out  = (float4*)d_out;

    const int threads = 256;
    const int blocks  = CHUNK / threads;   // 2^23 / 256 = 32768, exact
    convert2image_gather4<<<blocks, threads>>>(src, slic, out);
}